// round 1
// baseline (speedup 1.0000x reference)
#include <cuda_runtime.h>
#include <math.h>

#define BB    4
#define LL    512
#define NROW  2048   // B*L
#define HIN   128
#define DRAW  16
#define HID   64
#define HIDM  32
#define EMB   8

// ---------------- scratch (device globals; no allocation) ----------------
__device__ float g_zt[NROW*HID];
__device__ float g_si[NROW*HIDM];
__device__ float g_sj[NROW*HIDM];
__device__ float g_wh[NROW*HID];
__device__ float g_u1[NROW];
__device__ float g_u2[NROW];
__device__ float g_sdp[4*HIDM];
__device__ float g_znorm[NROW*HID];
__device__ float g_qn[NROW*HID];
__device__ float g_kn[NROW*HID];
__device__ float g_rowsum[NROW];
__device__ float g_colsum[NROW];
__device__ float g_diag[NROW];
__device__ float g_meanacc[HID];
__device__ float g_c[HID];
__device__ float g_scal[2];   // [0]=scatter dot sum, [1]=time sum

// Fast exp on FMA pipe (cephes exp2f poly); valid for |x| <~ 80.
__device__ __forceinline__ float fexp(float x){
    float y = x * 1.44269504088896341f;
    float n = rintf(y);
    float f = y - n;
    float p = 1.535336188319500e-4f;
    p = fmaf(p, f, 1.339887440266574e-3f);
    p = fmaf(p, f, 9.618437357674640e-3f);
    p = fmaf(p, f, 5.550332471162809e-2f);
    p = fmaf(p, f, 2.402264791363012e-1f);
    p = fmaf(p, f, 6.931472028550421e-1f);
    p = fmaf(p, f, 1.0f);
    int e = (int)n;
    return p * __int_as_float((e + 127) << 23);
}

__device__ __forceinline__ float blockReduce64(float v, float* red, int tid){
    __syncthreads();            // protect red from previous use
    red[tid] = v;
    __syncthreads();
    #pragma unroll
    for (int s = 32; s > 0; s >>= 1){
        if (tid < s) red[tid] += red[tid + s];
        __syncthreads();
    }
    return red[0];
}

// ---------------- K0: zero accumulators + precompute sd projection ----------------
__global__ void k_init(const float* __restrict__ dt_emb, const float* __restrict__ Wm1){
    int idx = blockIdx.x * blockDim.x + threadIdx.x;
    if (idx < NROW){ g_rowsum[idx] = 0.f; g_colsum[idx] = 0.f; }
    if (idx < HID)  g_meanacc[idx] = 0.f;
    if (idx < 2)    g_scal[idx] = 0.f;
    if (idx < 4*HIDM){
        int t = idx / HIDM, m = idx % HIDM;
        float s = 0.f;
        #pragma unroll
        for (int e = 0; e < EMB; e++)
            s = fmaf(dt_emb[t*EMB + e], Wm1[(2*DRAW + e)*HIDM + m], s);
        g_sdp[idx] = s;
    }
}

// ---------------- K1: per-row features: z_t, si, sj, Wh, u1, u2 ----------------
__global__ void k_feat(const float* __restrict__ h, const float* __restrict__ x_raw,
                       const float* __restrict__ W_in, const float* __restrict__ b_in,
                       const float* __restrict__ Wm1, const float* __restrict__ Wg,
                       const float* __restrict__ a1, const float* __restrict__ a2){
    __shared__ float hs[HIN];
    __shared__ float xs[DRAW];
    __shared__ float zts[HID];
    __shared__ float red[HID];
    int r = blockIdx.x, tid = threadIdx.x;

    hs[tid]      = h[r*HIN + tid];
    hs[tid + 64] = h[r*HIN + tid + 64];
    if (tid < DRAW) xs[tid] = x_raw[r*DRAW + tid];
    __syncthreads();

    float acc = b_in[tid];
    #pragma unroll
    for (int k = 0; k < HIN; k++) acc = fmaf(hs[k], W_in[k*HID + tid], acc);
    float zt = fmaxf(acc, 0.f);
    zts[tid] = zt;
    g_zt[r*HID + tid] = zt;

    if (tid < HIDM){
        float s = 0.f;
        #pragma unroll
        for (int q = 0; q < DRAW; q++) s = fmaf(xs[q], Wm1[q*HIDM + tid], s);
        g_si[r*HIDM + tid] = s;
    } else {
        int m = tid - HIDM;
        float s = 0.f;
        #pragma unroll
        for (int q = 0; q < DRAW; q++) s = fmaf(xs[q], Wm1[(DRAW + q)*HIDM + m], s);
        g_sj[r*HIDM + m] = s;
    }
    __syncthreads();

    float wh = 0.f;
    #pragma unroll
    for (int k = 0; k < HID; k++) wh = fmaf(zts[k], Wg[k*HID + tid], wh);
    g_wh[r*HID + tid] = wh;

    float u1 = blockReduce64(wh * a1[tid], red, tid);
    float u2 = blockReduce64(wh * a2[tid], red, tid);
    if (tid == 0){ g_u1[r] = u1; g_u2[r] = u2; }
}

// ---------------- K2: banded attention -> z_g, z, z_norm, qn, kn, mean-acc ----------------
__global__ void k_attn(const float* __restrict__ bm1, const float* __restrict__ Wm2,
                       const float* __restrict__ bm2, const float* __restrict__ Wf,
                       const float* __restrict__ bf){
    __shared__ float zts[HID];
    __shared__ float cs[2*HID];
    __shared__ float es[8];
    __shared__ float attn[8];
    __shared__ float red[HID];
    int r = blockIdx.x, tid = threadIdx.x;
    int b = r >> 9, i = r & 511;

    zts[tid] = g_zt[r*HID + tid];
    __syncthreads();

    if (tid < 7){
        int j = i - 3 + tid;
        float e = -1e30f;
        if (j >= 0 && j < LL){
            int dtv = 3 - tid; if (dtv < 0) dtv = 0;
            int rj = b*LL + j;
            float s = 0.f;
            #pragma unroll
            for (int m = 0; m < HIDM; m++){
                float v = g_si[r*HIDM + m] + g_sj[rj*HIDM + m] + g_sdp[dtv*HIDM + m] + bm1[m];
                if (v > 0.f) s = fmaf(v, Wm2[m], s);
            }
            float bias = s + bm2[0];
            float u = g_u1[r] + g_u2[rj];
            float lr = (u > 0.f) ? u : 0.2f * u;
            e = lr + bias - 0.2f * (float)dtv;
        }
        es[tid] = e;
    }
    __syncthreads();
    if (tid == 0){
        float mx = -1e30f;
        #pragma unroll
        for (int o = 0; o < 7; o++) mx = fmaxf(mx, es[o]);
        float ssum = 0.f; float ex[7];
        #pragma unroll
        for (int o = 0; o < 7; o++){
            ex[o] = (es[o] > -1e29f) ? __expf(es[o] - mx) : 0.f;
            ssum += ex[o];
        }
        float inv = 1.f / ssum;
        #pragma unroll
        for (int o = 0; o < 7; o++) attn[o] = ex[o] * inv;
    }
    __syncthreads();

    float acc = 0.f;
    #pragma unroll
    for (int o = 0; o < 7; o++){
        int j = i - 3 + o;
        int jc = j < 0 ? 0 : (j > LL-1 ? LL-1 : j);
        acc = fmaf(attn[o], g_wh[(b*LL + jc)*HID + tid], acc);
    }
    float zg = (acc > 0.f) ? acc : expm1f(acc);

    cs[tid]       = zts[tid];
    cs[HID + tid] = zg;
    __syncthreads();

    float z = bf[tid];
    #pragma unroll
    for (int k = 0; k < 2*HID; k++) z = fmaf(cs[k], Wf[k*HID + tid], z);
    z = fmaxf(z, 0.f);

    float nz  = blockReduce64(z*z,              red, tid);
    float nzt = blockReduce64(zts[tid]*zts[tid],red, tid);
    float nzg = blockReduce64(zg*zg,            red, tid);

    float zn = z / fmaxf(sqrtf(nz), 1e-8f);
    g_znorm[r*HID + tid] = zn;
    atomicAdd(&g_meanacc[tid], zn);
    g_qn[r*HID + tid] = zts[tid] / fmaxf(sqrtf(nzt), 1e-8f);
    g_kn[r*HID + tid] = zg       / fmaxf(sqrtf(nzg), 1e-8f);
}

// ---------------- K3a: c = normalize(mean) ----------------
__global__ void k_center(){
    __shared__ float red[HID];
    int tid = threadIdx.x;
    float m = g_meanacc[tid] / (float)NROW;
    float n = blockReduce64(m*m, red, tid);
    g_c[tid] = m / fmaxf(sqrtf(n), 1e-8f);
}

// ---------------- K3b: scatter dot, adjacent cos, diag ----------------
__global__ void k_aux(){
    __shared__ float cshr[HID];
    __shared__ float red[256];
    int tid = threadIdx.x;
    int r = blockIdx.x * 256 + tid;
    if (tid < HID) cshr[tid] = g_c[tid];
    __syncthreads();

    const float* zr = &g_znorm[r*HID];
    const float* q  = &g_qn[r*HID];
    const float* kk = &g_kn[r*HID];
    float sdot = 0.f, dg = 0.f;
    #pragma unroll
    for (int k = 0; k < HID; k++){
        sdot = fmaf(zr[k], cshr[k], sdot);
        dg   = fmaf(q[k], kk[k], dg);
    }
    g_diag[r] = dg * 10.f;   // 1/TEMP

    float tacc = 0.f;
    if ((r & 511) != 511){
        float tcos = 0.f;
        #pragma unroll
        for (int k = 0; k < HID; k++) tcos = fmaf(zr[k], zr[k + HID], tcos);
        float d = 1.f - tcos;
        tacc = d * d;
    }

    red[tid] = sdot; __syncthreads();
    #pragma unroll
    for (int s = 128; s > 0; s >>= 1){ if (tid < s) red[tid] += red[tid + s]; __syncthreads(); }
    if (tid == 0) atomicAdd(&g_scal[0], red[0]);
    __syncthreads();
    red[tid] = tacc; __syncthreads();
    #pragma unroll
    for (int s = 128; s > 0; s >>= 1){ if (tid < s) red[tid] += red[tid + s]; __syncthreads(); }
    if (tid == 0) atomicAdd(&g_scal[1], red[0]);
}

// ---------------- K4: logits = qn@knT/T : single-pass row & col exp-sums ----------------
// 64x64 tile per block, 4x4 register micro-tile, k-major swizzled smem.
__global__ void k_logits(){
    __shared__ float qT[64*64];
    __shared__ float kT[64*64];
    __shared__ float rowAcc[64];
    __shared__ float colAcc[64];
    int t  = threadIdx.x;
    int rb = blockIdx.x * 64, cb = blockIdx.y * 64;

    for (int idx = t; idx < 4096; idx += 256){
        int i = idx >> 6, k = idx & 63;
        int sw = (k & 15) << 2;
        qT[k*64 + (i ^ sw)] = g_qn[(rb + i)*64 + k];
        kT[k*64 + (i ^ sw)] = g_kn[(cb + i)*64 + k];
    }
    if (t < 64){ rowAcc[t] = 0.f; colAcc[t] = 0.f; }
    __syncthreads();

    int tx = t & 15, ty = t >> 4;
    float acc[4][4];
    #pragma unroll
    for (int a = 0; a < 4; a++)
        #pragma unroll
        for (int c = 0; c < 4; c++) acc[a][c] = 0.f;

    #pragma unroll 4
    for (int k = 0; k < 64; k++){
        int sw = (k & 15) << 2;
        float4 aq = *(const float4*)&qT[k*64 + ((ty*4) ^ sw)];
        float4 bk = *(const float4*)&kT[k*64 + ((tx*4) ^ sw)];
        float av[4] = {aq.x, aq.y, aq.z, aq.w};
        float bv[4] = {bk.x, bk.y, bk.z, bk.w};
        #pragma unroll
        for (int a = 0; a < 4; a++)
            #pragma unroll
            for (int c = 0; c < 4; c++)
                acc[a][c] = fmaf(av[a], bv[c], acc[a][c]);
    }

    float rs[4] = {0.f,0.f,0.f,0.f};
    float csm[4] = {0.f,0.f,0.f,0.f};
    #pragma unroll
    for (int a = 0; a < 4; a++)
        #pragma unroll
        for (int c = 0; c < 4; c++){
            float p = fexp(acc[a][c] * 10.f);   // 1/TEMP
            rs[a] += p; csm[c] += p;
        }
    #pragma unroll
    for (int a = 0; a < 4; a++) atomicAdd(&rowAcc[ty*4 + a], rs[a]);
    #pragma unroll
    for (int c = 0; c < 4; c++) atomicAdd(&colAcc[tx*4 + c], csm[c]);
    __syncthreads();
    if (t < 64){
        atomicAdd(&g_rowsum[rb + t], rowAcc[t]);
        atomicAdd(&g_colsum[cb + t], colAcc[t]);
    }
}

// ---------------- K5: final combine ----------------
__global__ void k_final(float* __restrict__ out){
    __shared__ float red[256];
    int t = threadIdx.x;
    float s = 0.f;
    for (int r = t; r < NROW; r += 256){
        s += (logf(g_rowsum[r]) - g_diag[r]) + (logf(g_colsum[r]) - g_diag[r]);
    }
    red[t] = s; __syncthreads();
    #pragma unroll
    for (int k = 128; k > 0; k >>= 1){ if (t < k) red[t] += red[t + k]; __syncthreads(); }
    if (t == 0){
        float l_con = 0.5f * red[0] / (float)NROW;
        float l_sc  = -g_scal[0] / (float)NROW;
        float l_t   =  g_scal[1] / (float)(BB * (LL - 1));
        out[0] = l_con + l_sc + l_t;
        out[1] = l_con;
        out[2] = l_sc;
        out[3] = l_t;
    }
}

// ---------------- launch ----------------
extern "C" void kernel_launch(void* const* d_in, const int* in_sizes, int n_in,
                              void* d_out, int out_size){
    const float* h      = (const float*)d_in[0];
    const float* x_raw  = (const float*)d_in[1];
    const float* W_in   = (const float*)d_in[2];
    const float* b_in   = (const float*)d_in[3];
    const float* dt_emb = (const float*)d_in[4];
    const float* Wm1    = (const float*)d_in[5];
    const float* bm1    = (const float*)d_in[6];
    const float* Wm2    = (const float*)d_in[7];
    const float* bm2    = (const float*)d_in[8];
    const float* Wg     = (const float*)d_in[9];
    const float* a1     = (const float*)d_in[10];
    const float* a2     = (const float*)d_in[11];
    const float* Wf     = (const float*)d_in[12];
    const float* bf     = (const float*)d_in[13];
    float* out = (float*)d_out;

    k_init<<<8, 256>>>(dt_emb, Wm1);
    k_feat<<<NROW, 64>>>(h, x_raw, W_in, b_in, Wm1, Wg, a1, a2);
    k_attn<<<NROW, 64>>>(bm1, Wm2, bm2, Wf, bf);
    k_center<<<1, 64>>>();
    k_aux<<<8, 256>>>();
    k_logits<<<dim3(32, 32), 256>>>();
    k_final<<<1, 256>>>(out);
}

// round 2
// speedup vs baseline: 1.4167x; 1.4167x over previous
#include <cuda_runtime.h>
#include <math.h>

#define NROW 2048
#define HID  64
#define HIDM 32
#define DRAW 16
#define HIN  128
#define EMB  8

// ---------------- scratch (device globals) ----------------
__device__ float g_zt[NROW*HID];
__device__ float g_si[NROW*HIDM];
__device__ float g_sj[NROW*HIDM];
__device__ float g_wh[NROW*HID];
__device__ float g_u1[NROW];
__device__ float g_u2[NROW];
__device__ float g_sdp[4*HIDM];
__device__ float g_znorm[NROW*HID];
__device__ float g_qn[NROW*HID];
__device__ float g_kn[NROW*HID];
__device__ float g_rowsum[NROW];
__device__ float g_colsum[NROW];
__device__ float g_diag[NROW];
__device__ float g_meanacc[HID];
__device__ float g_scal[2];
__device__ unsigned int g_cnt = 0;
__device__ unsigned int g_gen = 0;

// Generation-based grid barrier: no reset needed across graph replays.
__device__ __forceinline__ void gsync(int G){
    __threadfence();
    __syncthreads();
    if (threadIdx.x == 0){
        unsigned my = *(volatile unsigned*)&g_gen;
        unsigned old = atomicAdd(&g_cnt, 1u);
        if (old == (unsigned)G - 1u){
            g_cnt = 0;
            __threadfence();
            atomicAdd(&g_gen, 1u);
        } else {
            while (*(volatile unsigned*)&g_gen == my) __nanosleep(64);
        }
    }
    __syncthreads();
    __threadfence();
}

#define DOT4(acc, w0,w1,w2,w3, v) \
    acc = fmaf(w0,(v).x,fmaf(w1,(v).y,fmaf(w2,(v).z,fmaf(w3,(v).w,acc))));

__global__ void __launch_bounds__(256, 2)
fused_kernel(const float* __restrict__ h,      const float* __restrict__ x_raw,
             const float* __restrict__ W_in,   const float* __restrict__ b_in,
             const float* __restrict__ dt_emb, const float* __restrict__ Wm1,
             const float* __restrict__ bm1,    const float* __restrict__ Wm2,
             const float* __restrict__ bm2,    const float* __restrict__ Wg,
             const float* __restrict__ a1,     const float* __restrict__ a2,
             const float* __restrict__ Wf,     const float* __restrict__ bf,
             float* __restrict__ out)
{
    __shared__ float smA[4096];   // 16KB: qT | feat/attn staging
    __shared__ float smB[4096];   // 16KB: kT | wh-neighbors, z
    __shared__ float smC[1024];   // 4KB : partial-sum reduction
    __shared__ float smD[1024];   // 4KB : params, es, attn, norms, rowAcc/colAcc, red

    const int tid  = threadIdx.x;
    const int bid  = blockIdx.x;
    const int G    = gridDim.x;
    const int lane = tid & 31;
    const int wid  = tid >> 5;
    const int c    = tid & 63;
    const int quad = tid >> 6;     // 0..3: row index or k-quarter

    // ================= PHASE 0: init + feat =================
    for (int i = bid*256 + tid; i < NROW; i += G*256){
        g_rowsum[i] = 0.f; g_colsum[i] = 0.f;
    }
    if (bid == 0){
        if (tid < HID) g_meanacc[tid] = 0.f;
        if (tid < 2)   g_scal[tid] = 0.f;
        if (tid < 128){
            int t = tid >> 5, m = tid & 31;
            float s = 0.f;
            #pragma unroll
            for (int e = 0; e < EMB; e++)
                s = fmaf(dt_emb[t*EMB+e], Wm1[(2*DRAW+e)*HIDM+m], s);
            g_sdp[tid] = s;
        }
    }

    for (int base = bid*4; base < NROW; base += G*4){
        // stage h (4x128) and x (4x16)
        for (int idx = tid; idx < 512; idx += 256)
            smA[idx] = h[(base + (idx>>7))*HIN + (idx & 127)];
        if (tid < 64) smA[512 + tid] = x_raw[base*DRAW + tid];
        __syncthreads();

        // z_t = relu(h @ W_in + b): thread (c, kh=quad) does 4 rows, 32 k's
        {
            float p0=0.f, p1=0.f, p2=0.f, p3=0.f;
            const float4* h4 = (const float4*)smA;
            #pragma unroll
            for (int kk = 0; kk < 8; kk++){
                int kb = quad*32 + kk*4;
                float w0 = W_in[(kb+0)*64 + c];
                float w1 = W_in[(kb+1)*64 + c];
                float w2 = W_in[(kb+2)*64 + c];
                float w3 = W_in[(kb+3)*64 + c];
                float4 v0 = h4[0*32 + (kb>>2)];
                float4 v1 = h4[1*32 + (kb>>2)];
                float4 v2 = h4[2*32 + (kb>>2)];
                float4 v3 = h4[3*32 + (kb>>2)];
                DOT4(p0, w0,w1,w2,w3, v0);
                DOT4(p1, w0,w1,w2,w3, v1);
                DOT4(p2, w0,w1,w2,w3, v2);
                DOT4(p3, w0,w1,w2,w3, v3);
            }
            smC[(quad*4+0)*64 + c] = p0;
            smC[(quad*4+1)*64 + c] = p1;
            smC[(quad*4+2)*64 + c] = p2;
            smC[(quad*4+3)*64 + c] = p3;
        }
        __syncthreads();
        {
            int r = quad;
            float z = b_in[c] + smC[(0*4+r)*64+c] + smC[(1*4+r)*64+c]
                              + smC[(2*4+r)*64+c] + smC[(3*4+r)*64+c];
            z = fmaxf(z, 0.f);
            smB[r*64 + c] = z;
            g_zt[(base+r)*64 + c] = z;

            // si / sj: 4 rows x 64 outputs
            int m   = c & 31;
            int off = (c < 32) ? 0 : DRAW;
            float s = 0.f;
            #pragma unroll
            for (int q = 0; q < DRAW; q++)
                s = fmaf(smA[512 + r*16 + q], Wm1[(off+q)*HIDM + m], s);
            if (c < 32) g_si[(base+r)*32 + m] = s;
            else        g_sj[(base+r)*32 + m] = s;
        }
        __syncthreads();

        // Wh = z_t @ Wg: K=64, thread (c, kh=quad) 16 k's
        {
            float p0=0.f, p1=0.f, p2=0.f, p3=0.f;
            const float4* z4 = (const float4*)smB;
            #pragma unroll
            for (int kk = 0; kk < 4; kk++){
                int kb = quad*16 + kk*4;
                float w0 = Wg[(kb+0)*64 + c];
                float w1 = Wg[(kb+1)*64 + c];
                float w2 = Wg[(kb+2)*64 + c];
                float w3 = Wg[(kb+3)*64 + c];
                float4 v0 = z4[0*16 + (kb>>2)];
                float4 v1 = z4[1*16 + (kb>>2)];
                float4 v2 = z4[2*16 + (kb>>2)];
                float4 v3 = z4[3*16 + (kb>>2)];
                DOT4(p0, w0,w1,w2,w3, v0);
                DOT4(p1, w0,w1,w2,w3, v1);
                DOT4(p2, w0,w1,w2,w3, v2);
                DOT4(p3, w0,w1,w2,w3, v3);
            }
            smC[(quad*4+0)*64 + c] = p0;
            smC[(quad*4+1)*64 + c] = p1;
            smC[(quad*4+2)*64 + c] = p2;
            smC[(quad*4+3)*64 + c] = p3;
        }
        __syncthreads();
        {
            int r = quad;
            float whv = smC[(0*4+r)*64+c] + smC[(1*4+r)*64+c]
                      + smC[(2*4+r)*64+c] + smC[(3*4+r)*64+c];
            smB[256 + r*64 + c] = whv;
            g_wh[(base+r)*64 + c] = whv;
        }
        __syncthreads();
        // u1/u2: warp w -> row (w&3), which (w>>2)
        {
            int r = wid & 3, sel = wid >> 2;
            const float* av = sel ? a2 : a1;
            float v = smB[256 + r*64 + lane]      * av[lane]
                    + smB[256 + r*64 + lane + 32] * av[lane+32];
            #pragma unroll
            for (int s = 16; s > 0; s >>= 1) v += __shfl_down_sync(0xffffffffu, v, s);
            if (lane == 0){
                if (sel) g_u2[base+r] = v; else g_u1[base+r] = v;
            }
        }
        __syncthreads();
    }

    gsync(G);

    // ================= PHASE 1: attn =================
    // stage constants once
    if (tid < 128)                 smD[tid]       = g_sdp[tid];
    else if (tid < 160)            smD[tid]       = bm1[tid-128];
    else if (tid < 192)            smD[tid]       = Wm2[tid-160];
    const float bm2v = bm2[0];
    __syncthreads();

    for (int base = bid*4; base < NROW; base += G*4){
        const int b  = base >> 9;
        const int i0 = base & 511;
        const int lo = b << 9, hi = lo + 511;

        {   // zt rows -> smA[0..255] and cs[r][0..63] at smA[256 + r*128]
            float v = g_zt[base*64 + tid];
            smA[tid] = v;
            smA[256 + quad*128 + c] = v;
        }
        if (tid < 128) smA[768 + tid] = g_si[base*32 + tid];
        for (int idx = tid; idx < 320; idx += 256){
            int jj = idx >> 5, m = idx & 31;
            int j = base - 3 + jj; j = j < lo ? lo : (j > hi ? hi : j);
            smA[896 + idx] = g_sj[j*32 + m];
        }
        for (int idx = tid; idx < 640; idx += 256){
            int jj = idx >> 6, cc = idx & 63;
            int j = base - 3 + jj; j = j < lo ? lo : (j > hi ? hi : j);
            smB[jj*64 + cc] = g_wh[j*64 + cc];
        }
        if (tid < 10){
            int j = base - 3 + tid; j = j < lo ? lo : (j > hi ? hi : j);
            smD[256 + tid] = g_u2[j];
        }
        if (tid >= 16 && tid < 20) smD[266 + tid - 16] = g_u1[base + tid - 16];
        __syncthreads();

        // bias: 28 warp-tasks (rr, o)
        for (int t = wid; t < 28; t += 8){
            int rr = t / 7, o = t % 7;
            int i = i0 + rr, j = i - 3 + o;
            int jj = rr + o;
            int dtv = 3 - o; if (dtv < 0) dtv = 0;
            float v = smA[768 + rr*32 + lane] + smA[896 + jj*32 + lane]
                    + smD[dtv*32 + lane] + smD[128 + lane];
            float p = v > 0.f ? v * smD[160 + lane] : 0.f;
            #pragma unroll
            for (int s = 16; s > 0; s >>= 1) p += __shfl_down_sync(0xffffffffu, p, s);
            if (lane == 0){
                float e = -1e30f;
                if (j >= 0 && j < 512){
                    float u  = smD[266 + rr] + smD[256 + jj];
                    float lr = u > 0.f ? u : 0.2f*u;
                    e = lr + p + bm2v - 0.2f*(float)dtv;
                }
                smD[192 + rr*8 + o] = e;
            }
        }
        __syncthreads();
        if (tid < 4){
            float mx = -1e30f;
            #pragma unroll
            for (int o = 0; o < 7; o++) mx = fmaxf(mx, smD[192 + tid*8 + o]);
            float sm = 0.f, ex[7];
            #pragma unroll
            for (int o = 0; o < 7; o++){
                float e = smD[192 + tid*8 + o];
                ex[o] = e > -1e29f ? __expf(e - mx) : 0.f;
                sm += ex[o];
            }
            float inv = 1.f / sm;
            #pragma unroll
            for (int o = 0; o < 7; o++) smD[224 + tid*8 + o] = ex[o]*inv;
        }
        __syncthreads();

        // z_g = elu(attn @ Wh)
        {
            int r = quad;
            float acc = 0.f;
            #pragma unroll
            for (int o = 0; o < 7; o++)
                acc = fmaf(smD[224 + r*8 + o], smB[(r+o)*64 + c], acc);
            float zg = acc > 0.f ? acc : expm1f(acc);
            smA[256 + r*128 + 64 + c] = zg;
        }
        __syncthreads();

        // z = relu([z_t,z_g] @ Wf + bf): K=128, thread (c, kh=quad) 32 k's
        {
            float p0=0.f, p1=0.f, p2=0.f, p3=0.f;
            const float4* cs4 = (const float4*)(smA + 256);
            #pragma unroll
            for (int kk = 0; kk < 8; kk++){
                int kb = quad*32 + kk*4;
                float w0 = Wf[(kb+0)*64 + c];
                float w1 = Wf[(kb+1)*64 + c];
                float w2 = Wf[(kb+2)*64 + c];
                float w3 = Wf[(kb+3)*64 + c];
                float4 v0 = cs4[0*32 + (kb>>2)];
                float4 v1 = cs4[1*32 + (kb>>2)];
                float4 v2 = cs4[2*32 + (kb>>2)];
                float4 v3 = cs4[3*32 + (kb>>2)];
                DOT4(p0, w0,w1,w2,w3, v0);
                DOT4(p1, w0,w1,w2,w3, v1);
                DOT4(p2, w0,w1,w2,w3, v2);
                DOT4(p3, w0,w1,w2,w3, v3);
            }
            smC[(quad*4+0)*64 + c] = p0;
            smC[(quad*4+1)*64 + c] = p1;
            smC[(quad*4+2)*64 + c] = p2;
            smC[(quad*4+3)*64 + c] = p3;
        }
        __syncthreads();
        {
            int r = quad;
            float z = bf[c] + smC[(0*4+r)*64+c] + smC[(1*4+r)*64+c]
                            + smC[(2*4+r)*64+c] + smC[(3*4+r)*64+c];
            smB[640 + r*64 + c] = fmaxf(z, 0.f);
        }
        __syncthreads();

        // norms: 16 warp-tasks: which(0..3) x row
        for (int t = wid; t < 16; t += 8){
            int which = t >> 2, r = t & 3;
            float v;
            if (which == 0){
                float x1 = smB[640 + r*64 + lane], x2 = smB[640 + r*64 + lane + 32];
                v = x1*x1 + x2*x2;
            } else if (which == 1){
                float x1 = smA[r*64 + lane], x2 = smA[r*64 + lane + 32];
                v = x1*x1 + x2*x2;
            } else if (which == 2){
                float x1 = smA[256 + r*128 + 64 + lane], x2 = smA[256 + r*128 + 96 + lane];
                v = x1*x1 + x2*x2;
            } else {
                v = smA[r*64 + lane]      * smA[256 + r*128 + 64 + lane]
                  + smA[r*64 + lane + 32] * smA[256 + r*128 + 96 + lane];
            }
            #pragma unroll
            for (int s = 16; s > 0; s >>= 1) v += __shfl_down_sync(0xffffffffu, v, s);
            if (lane == 0) smD[270 + t] = v;
        }
        __syncthreads();
        {
            int r = quad;
            float invz  = 1.f / fmaxf(sqrtf(smD[270 + 0  + r]), 1e-8f);
            float invzt = 1.f / fmaxf(sqrtf(smD[270 + 4  + r]), 1e-8f);
            float invzg = 1.f / fmaxf(sqrtf(smD[270 + 8  + r]), 1e-8f);
            g_znorm[(base+r)*64 + c] = smB[640 + r*64 + c] * invz;
            g_qn[(base+r)*64 + c]    = smA[r*64 + c] * invzt;
            g_kn[(base+r)*64 + c]    = smA[256 + r*128 + 64 + c] * invzg;
            if (c == 0) g_diag[base+r] = 10.f * smD[270 + 12 + r] * invzt * invzg;
        }
        if (tid < 64){
            float ms = 0.f;
            #pragma unroll
            for (int r = 0; r < 4; r++){
                float invz = 1.f / fmaxf(sqrtf(smD[270 + r]), 1e-8f);
                ms += smB[640 + r*64 + tid] * invz;
            }
            atomicAdd(&g_meanacc[tid], ms);
        }
        __syncthreads();
    }

    gsync(G);

    // ================= PHASE 2a: aux (center, scatter, time) =================
    if (tid < 64) smD[288 + tid] = __ldcg(&g_meanacc[tid]) * (1.f/2048.f);
    __syncthreads();
    if (wid == 0){
        float m1 = smD[288 + lane], m2 = smD[288 + lane + 32];
        float v = m1*m1 + m2*m2;
        #pragma unroll
        for (int s = 16; s > 0; s >>= 1) v += __shfl_down_sync(0xffffffffu, v, s);
        if (lane == 0) smD[286] = v;
    }
    __syncthreads();
    if (tid < 64){
        float inv = 1.f / fmaxf(sqrtf(smD[286]), 1e-8f);
        smD[352 + tid] = smD[288 + tid] * inv;
    }
    __syncthreads();

    float sdacc = 0.f;   // per-lane
    float tacc  = 0.f;   // lane0-of-warp
    for (int r = bid*8 + wid; r < NROW; r += G*8){
        float z1 = g_znorm[r*64 + lane];
        float z2 = g_znorm[r*64 + lane + 32];
        sdacc = fmaf(z1, smD[352+lane], fmaf(z2, smD[352+lane+32], sdacc));
        if ((r & 511) != 511){
            float y1 = g_znorm[(r+1)*64 + lane];
            float y2 = g_znorm[(r+1)*64 + lane + 32];
            float d = fmaf(z1, y1, z2*y2);
            #pragma unroll
            for (int s = 16; s > 0; s >>= 1) d += __shfl_down_sync(0xffffffffu, d, s);
            if (lane == 0){ float dd = 1.f - d; tacc = fmaf(dd, dd, tacc); }
        }
    }
    __syncthreads();
    smD[544 + tid] = sdacc; __syncthreads();
    #pragma unroll
    for (int s = 128; s > 0; s >>= 1){ if (tid < s) smD[544+tid] += smD[544+tid+s]; __syncthreads(); }
    if (tid == 0) atomicAdd(&g_scal[0], smD[544]);
    __syncthreads();
    smD[544 + tid] = (lane == 0) ? tacc : 0.f; __syncthreads();
    #pragma unroll
    for (int s = 128; s > 0; s >>= 1){ if (tid < s) smD[544+tid] += smD[544+tid+s]; __syncthreads(); }
    if (tid == 0) atomicAdd(&g_scal[1], smD[544]);
    __syncthreads();

    // ================= PHASE 2b: logits row/col exp-sums =================
    for (int tI = bid; tI < 1024; tI += G){
        int rb = (tI & 31) << 6, cb = (tI >> 5) << 6;
        for (int idx = tid; idx < 1024; idx += 256){
            int i = idx >> 4, kq = (idx & 15) << 2;
            float4 q4 = *(const float4*)&g_qn[(rb+i)*64 + kq];
            float4 k4 = *(const float4*)&g_kn[(cb+i)*64 + kq];
            smA[(kq+0)*64 + (i ^ (((kq+0)&15)<<2))] = q4.x;
            smA[(kq+1)*64 + (i ^ (((kq+1)&15)<<2))] = q4.y;
            smA[(kq+2)*64 + (i ^ (((kq+2)&15)<<2))] = q4.z;
            smA[(kq+3)*64 + (i ^ (((kq+3)&15)<<2))] = q4.w;
            smB[(kq+0)*64 + (i ^ (((kq+0)&15)<<2))] = k4.x;
            smB[(kq+1)*64 + (i ^ (((kq+1)&15)<<2))] = k4.y;
            smB[(kq+2)*64 + (i ^ (((kq+2)&15)<<2))] = k4.z;
            smB[(kq+3)*64 + (i ^ (((kq+3)&15)<<2))] = k4.w;
        }
        if (tid < 64){ smD[416+tid] = 0.f; smD[480+tid] = 0.f; }
        __syncthreads();

        int tx = tid & 15, ty = tid >> 4;
        float acc[4][4];
        #pragma unroll
        for (int a = 0; a < 4; a++)
            #pragma unroll
            for (int d = 0; d < 4; d++) acc[a][d] = 0.f;

        #pragma unroll 4
        for (int k = 0; k < 64; k++){
            int sw = (k & 15) << 2;
            float4 aq = *(const float4*)&smA[k*64 + ((ty*4) ^ sw)];
            float4 bk = *(const float4*)&smB[k*64 + ((tx*4) ^ sw)];
            float av[4] = {aq.x, aq.y, aq.z, aq.w};
            float bv[4] = {bk.x, bk.y, bk.z, bk.w};
            #pragma unroll
            for (int a = 0; a < 4; a++)
                #pragma unroll
                for (int d = 0; d < 4; d++)
                    acc[a][d] = fmaf(av[a], bv[d], acc[a][d]);
        }

        float rs[4]  = {0.f,0.f,0.f,0.f};
        float csm[4] = {0.f,0.f,0.f,0.f};
        #pragma unroll
        for (int a = 0; a < 4; a++)
            #pragma unroll
            for (int d = 0; d < 4; d++){
                float p = __expf(acc[a][d] * 10.f);
                rs[a] += p; csm[d] += p;
            }
        #pragma unroll
        for (int a = 0; a < 4; a++) atomicAdd(&smD[416 + ty*4 + a], rs[a]);
        #pragma unroll
        for (int d = 0; d < 4; d++) atomicAdd(&smD[480 + tx*4 + d], csm[d]);
        __syncthreads();
        if (tid < 64){
            atomicAdd(&g_rowsum[rb + tid], smD[416 + tid]);
            atomicAdd(&g_colsum[cb + tid], smD[480 + tid]);
        }
        __syncthreads();
    }

    gsync(G);

    // ================= PHASE 3: final =================
    if (bid == 0){
        float s = 0.f;
        for (int r = tid; r < NROW; r += 256){
            float rsm = __ldcg(&g_rowsum[r]);
            float csm = __ldcg(&g_colsum[r]);
            float dg  = __ldcg(&g_diag[r]);
            s += logf(rsm) + logf(csm) - 2.f*dg;
        }
        smD[544 + tid] = s; __syncthreads();
        #pragma unroll
        for (int k = 128; k > 0; k >>= 1){ if (tid < k) smD[544+tid] += smD[544+tid+k]; __syncthreads(); }
        if (tid == 0){
            float l_con = 0.5f * smD[544] / 2048.f;
            float l_sc  = -__ldcg(&g_scal[0]) / 2048.f;
            float l_t   =  __ldcg(&g_scal[1]) / (4.f * 511.f);
            out[0] = l_con + l_sc + l_t;
            out[1] = l_con;
            out[2] = l_sc;
            out[3] = l_t;
        }
    }
}

// ---------------- launch ----------------
extern "C" void kernel_launch(void* const* d_in, const int* in_sizes, int n_in,
                              void* d_out, int out_size){
    const float* h      = (const float*)d_in[0];
    const float* x_raw  = (const float*)d_in[1];
    const float* W_in   = (const float*)d_in[2];
    const float* b_in   = (const float*)d_in[3];
    const float* dt_emb = (const float*)d_in[4];
    const float* Wm1    = (const float*)d_in[5];
    const float* bm1    = (const float*)d_in[6];
    const float* Wm2    = (const float*)d_in[7];
    const float* bm2    = (const float*)d_in[8];
    const float* Wg     = (const float*)d_in[9];
    const float* a1     = (const float*)d_in[10];
    const float* a2     = (const float*)d_in[11];
    const float* Wf     = (const float*)d_in[12];
    const float* bf     = (const float*)d_in[13];
    float* out = (float*)d_out;

    int dev = 0; cudaGetDevice(&dev);
    int sms = 0;
    cudaDeviceGetAttribute(&sms, cudaDevAttrMultiProcessorCount, dev);
    if (sms <= 0) sms = 132;
    int G = sms * 2;   // __launch_bounds__(256,2) guarantees co-residency

    fused_kernel<<<G, 256>>>(h, x_raw, W_in, b_in, dt_emb, Wm1, bm1, Wm2, bm2,
                             Wg, a1, a2, Wf, bf, out);
}

// round 3
// speedup vs baseline: 2.0330x; 1.4350x over previous
#include <cuda_runtime.h>
#include <math.h>

#define NROW 2048
#define HID  64
#define HIDM 32
#define DRAW 16
#define HIN  128
#define EMB  8

// ---------------- scratch (device globals) ----------------
__device__ float g_zt[NROW*HID];
__device__ float g_si[NROW*HIDM];
__device__ float g_sj[NROW*HIDM];
__device__ float g_wh[NROW*HID];
__device__ float g_u1[NROW];
__device__ float g_u2[NROW];
__device__ float g_sdp[4*HIDM];
__device__ float g_znorm[NROW*HID];
__device__ float g_qn[NROW*HID];
__device__ float g_kn[NROW*HID];
__device__ float g_rowsum[NROW];
__device__ float g_colsum[NROW];
__device__ float g_diag[NROW];
__device__ float g_meanacc[HID];
__device__ float g_scal[2];
__device__ unsigned int g_cnt = 0;
__device__ unsigned int g_gen = 0;

// Generation-based grid barrier: no reset needed across graph replays.
__device__ __forceinline__ void gsync(int G){
    __threadfence();
    __syncthreads();
    if (threadIdx.x == 0){
        unsigned my = *(volatile unsigned*)&g_gen;
        unsigned old = atomicAdd(&g_cnt, 1u);
        if (old == (unsigned)G - 1u){
            g_cnt = 0;
            __threadfence();
            atomicAdd(&g_gen, 1u);
        } else {
            while (*(volatile unsigned*)&g_gen == my) __nanosleep(64);
        }
    }
    __syncthreads();
    __threadfence();
}

// Fast exp on FMA pipe (cephes exp2f poly); |x| <= ~80.
__device__ __forceinline__ float fexp(float x){
    float y = x * 1.44269504088896341f;
    float n = rintf(y);
    float f = y - n;
    float p = 1.535336188319500e-4f;
    p = fmaf(p, f, 1.339887440266574e-3f);
    p = fmaf(p, f, 9.618437357674640e-3f);
    p = fmaf(p, f, 5.550332471162809e-2f);
    p = fmaf(p, f, 2.402264791363012e-1f);
    p = fmaf(p, f, 6.931472028550421e-1f);
    p = fmaf(p, f, 1.0f);
    int e = (int)n;
    return p * __int_as_float((e + 127) << 23);
}

#define DOT4(acc, w0,w1,w2,w3, v) \
    acc = fmaf(w0,(v).x,fmaf(w1,(v).y,fmaf(w2,(v).z,fmaf(w3,(v).w,acc))));

__global__ void __launch_bounds__(256, 2)
fused_kernel(const float* __restrict__ h,      const float* __restrict__ x_raw,
             const float* __restrict__ W_in,   const float* __restrict__ b_in,
             const float* __restrict__ dt_emb, const float* __restrict__ Wm1,
             const float* __restrict__ bm1,    const float* __restrict__ Wm2,
             const float* __restrict__ bm2,    const float* __restrict__ Wg,
             const float* __restrict__ a1,     const float* __restrict__ a2,
             const float* __restrict__ Wf,     const float* __restrict__ bf,
             float* __restrict__ out)
{
    extern __shared__ float sm[];
    float* smA = sm;           // 4096 floats
    float* smB = sm + 4096;    // 4096
    float* smC = sm + 8192;    // 1024
    float* smD = sm + 9216;    // 1024
    // logits phase reuses: qT = sm (8192), kT = sm+8192 (8192), colPart = sm+16384 (2048)

    const int tid  = threadIdx.x;
    const int bid  = blockIdx.x;
    const int G    = gridDim.x;
    const int lane = tid & 31;
    const int wid  = tid >> 5;
    const int c    = tid & 63;
    const int quad = tid >> 6;     // 0..3

    // ================= PHASE 0: init + feat =================
    for (int i = bid*256 + tid; i < NROW; i += G*256){
        g_rowsum[i] = 0.f; g_colsum[i] = 0.f;
    }
    if (bid == 0){
        if (tid < HID) g_meanacc[tid] = 0.f;
        if (tid < 2)   g_scal[tid] = 0.f;
        if (tid < 128){
            int t = tid >> 5, m = tid & 31;
            float s = 0.f;
            #pragma unroll
            for (int e = 0; e < EMB; e++)
                s = fmaf(dt_emb[t*EMB+e], Wm1[(2*DRAW+e)*HIDM+m], s);
            g_sdp[tid] = s;
        }
    }

    for (int base = bid*4; base < NROW; base += G*4){
        for (int idx = tid; idx < 512; idx += 256)
            smA[idx] = h[(base + (idx>>7))*HIN + (idx & 127)];
        if (tid < 64) smA[512 + tid] = x_raw[base*DRAW + tid];
        __syncthreads();

        // z_t = relu(h @ W_in + b): thread (c, quad) = 4 rows, 32 k's
        {
            float p0=0.f, p1=0.f, p2=0.f, p3=0.f;
            const float4* h4 = (const float4*)smA;
            #pragma unroll
            for (int kk = 0; kk < 8; kk++){
                int kb = quad*32 + kk*4;
                float w0 = W_in[(kb+0)*64 + c];
                float w1 = W_in[(kb+1)*64 + c];
                float w2 = W_in[(kb+2)*64 + c];
                float w3 = W_in[(kb+3)*64 + c];
                float4 v0 = h4[0*32 + (kb>>2)];
                float4 v1 = h4[1*32 + (kb>>2)];
                float4 v2 = h4[2*32 + (kb>>2)];
                float4 v3 = h4[3*32 + (kb>>2)];
                DOT4(p0, w0,w1,w2,w3, v0);
                DOT4(p1, w0,w1,w2,w3, v1);
                DOT4(p2, w0,w1,w2,w3, v2);
                DOT4(p3, w0,w1,w2,w3, v3);
            }
            smC[(quad*4+0)*64 + c] = p0;
            smC[(quad*4+1)*64 + c] = p1;
            smC[(quad*4+2)*64 + c] = p2;
            smC[(quad*4+3)*64 + c] = p3;
        }
        __syncthreads();
        {
            int r = quad;
            float z = b_in[c] + smC[(0*4+r)*64+c] + smC[(1*4+r)*64+c]
                              + smC[(2*4+r)*64+c] + smC[(3*4+r)*64+c];
            z = fmaxf(z, 0.f);
            smB[r*64 + c] = z;
            g_zt[(base+r)*64 + c] = z;

            int m   = c & 31;
            int off = (c < 32) ? 0 : DRAW;
            float s = 0.f;
            #pragma unroll
            for (int q = 0; q < DRAW; q++)
                s = fmaf(smA[512 + r*16 + q], Wm1[(off+q)*HIDM + m], s);
            if (c < 32) g_si[(base+r)*32 + m] = s;
            else        g_sj[(base+r)*32 + m] = s;
        }
        __syncthreads();

        // Wh = z_t @ Wg
        {
            float p0=0.f, p1=0.f, p2=0.f, p3=0.f;
            const float4* z4 = (const float4*)smB;
            #pragma unroll
            for (int kk = 0; kk < 4; kk++){
                int kb = quad*16 + kk*4;
                float w0 = Wg[(kb+0)*64 + c];
                float w1 = Wg[(kb+1)*64 + c];
                float w2 = Wg[(kb+2)*64 + c];
                float w3 = Wg[(kb+3)*64 + c];
                float4 v0 = z4[0*16 + (kb>>2)];
                float4 v1 = z4[1*16 + (kb>>2)];
                float4 v2 = z4[2*16 + (kb>>2)];
                float4 v3 = z4[3*16 + (kb>>2)];
                DOT4(p0, w0,w1,w2,w3, v0);
                DOT4(p1, w0,w1,w2,w3, v1);
                DOT4(p2, w0,w1,w2,w3, v2);
                DOT4(p3, w0,w1,w2,w3, v3);
            }
            smC[(quad*4+0)*64 + c] = p0;
            smC[(quad*4+1)*64 + c] = p1;
            smC[(quad*4+2)*64 + c] = p2;
            smC[(quad*4+3)*64 + c] = p3;
        }
        __syncthreads();
        {
            int r = quad;
            float whv = smC[(0*4+r)*64+c] + smC[(1*4+r)*64+c]
                      + smC[(2*4+r)*64+c] + smC[(3*4+r)*64+c];
            smB[256 + r*64 + c] = whv;
            g_wh[(base+r)*64 + c] = whv;
        }
        __syncthreads();
        {
            int r = wid & 3, sel = wid >> 2;
            const float* av = sel ? a2 : a1;
            float v = smB[256 + r*64 + lane]      * av[lane]
                    + smB[256 + r*64 + lane + 32] * av[lane+32];
            #pragma unroll
            for (int s = 16; s > 0; s >>= 1) v += __shfl_down_sync(0xffffffffu, v, s);
            if (lane == 0){
                if (sel) g_u2[base+r] = v; else g_u1[base+r] = v;
            }
        }
        __syncthreads();
    }

    gsync(G);

    // ================= PHASE 1: attn =================
    if (tid < 128)                 smD[tid]       = g_sdp[tid];
    else if (tid < 160)            smD[tid]       = bm1[tid-128];
    else if (tid < 192)            smD[tid]       = Wm2[tid-160];
    const float bm2v = bm2[0];
    __syncthreads();

    for (int base = bid*4; base < NROW; base += G*4){
        const int i0 = base & 511;
        const int lo = base & ~511, hi = lo + 511;

        {
            float v = g_zt[base*64 + tid];
            smA[tid] = v;
            smA[256 + quad*128 + c] = v;
        }
        if (tid < 128) smA[768 + tid] = g_si[base*32 + tid];
        for (int idx = tid; idx < 320; idx += 256){
            int jj = idx >> 5, m = idx & 31;
            int j = base - 3 + jj; j = j < lo ? lo : (j > hi ? hi : j);
            smA[896 + idx] = g_sj[j*32 + m];
        }
        for (int idx = tid; idx < 640; idx += 256){
            int jj = idx >> 6, cc = idx & 63;
            int j = base - 3 + jj; j = j < lo ? lo : (j > hi ? hi : j);
            smB[jj*64 + cc] = g_wh[j*64 + cc];
        }
        if (tid < 10){
            int j = base - 3 + tid; j = j < lo ? lo : (j > hi ? hi : j);
            smD[256 + tid] = g_u2[j];
        }
        if (tid >= 16 && tid < 20) smD[266 + tid - 16] = g_u1[base + tid - 16];
        __syncthreads();

        for (int t = wid; t < 28; t += 8){
            int rr = t / 7, o = t % 7;
            int i = i0 + rr, j = i - 3 + o;
            int jj = rr + o;
            int dtv = 3 - o; if (dtv < 0) dtv = 0;
            float v = smA[768 + rr*32 + lane] + smA[896 + jj*32 + lane]
                    + smD[dtv*32 + lane] + smD[128 + lane];
            float p = v > 0.f ? v * smD[160 + lane] : 0.f;
            #pragma unroll
            for (int s = 16; s > 0; s >>= 1) p += __shfl_down_sync(0xffffffffu, p, s);
            if (lane == 0){
                float e = -1e30f;
                if (j >= 0 && j < 512){
                    float u  = smD[266 + rr] + smD[256 + jj];
                    float lr = u > 0.f ? u : 0.2f*u;
                    e = lr + p + bm2v - 0.2f*(float)dtv;
                }
                smD[192 + rr*8 + o] = e;
            }
        }
        __syncthreads();
        if (tid < 4){
            float mx = -1e30f;
            #pragma unroll
            for (int o = 0; o < 7; o++) mx = fmaxf(mx, smD[192 + tid*8 + o]);
            float sum = 0.f, ex[7];
            #pragma unroll
            for (int o = 0; o < 7; o++){
                float e = smD[192 + tid*8 + o];
                ex[o] = e > -1e29f ? fexp(e - mx) : 0.f;
                sum += ex[o];
            }
            float inv = 1.f / sum;
            #pragma unroll
            for (int o = 0; o < 7; o++) smD[224 + tid*8 + o] = ex[o]*inv;
        }
        __syncthreads();

        {
            int r = quad;
            float acc = 0.f;
            #pragma unroll
            for (int o = 0; o < 7; o++)
                acc = fmaf(smD[224 + r*8 + o], smB[(r+o)*64 + c], acc);
            float zg = acc > 0.f ? acc : expm1f(acc);
            smA[256 + r*128 + 64 + c] = zg;
        }
        __syncthreads();

        {
            float p0=0.f, p1=0.f, p2=0.f, p3=0.f;
            const float4* cs4 = (const float4*)(smA + 256);
            #pragma unroll
            for (int kk = 0; kk < 8; kk++){
                int kb = quad*32 + kk*4;
                float w0 = Wf[(kb+0)*64 + c];
                float w1 = Wf[(kb+1)*64 + c];
                float w2 = Wf[(kb+2)*64 + c];
                float w3 = Wf[(kb+3)*64 + c];
                float4 v0 = cs4[0*32 + (kb>>2)];
                float4 v1 = cs4[1*32 + (kb>>2)];
                float4 v2 = cs4[2*32 + (kb>>2)];
                float4 v3 = cs4[3*32 + (kb>>2)];
                DOT4(p0, w0,w1,w2,w3, v0);
                DOT4(p1, w0,w1,w2,w3, v1);
                DOT4(p2, w0,w1,w2,w3, v2);
                DOT4(p3, w0,w1,w2,w3, v3);
            }
            smC[(quad*4+0)*64 + c] = p0;
            smC[(quad*4+1)*64 + c] = p1;
            smC[(quad*4+2)*64 + c] = p2;
            smC[(quad*4+3)*64 + c] = p3;
        }
        __syncthreads();
        {
            int r = quad;
            float z = bf[c] + smC[(0*4+r)*64+c] + smC[(1*4+r)*64+c]
                            + smC[(2*4+r)*64+c] + smC[(3*4+r)*64+c];
            smB[640 + r*64 + c] = fmaxf(z, 0.f);
        }
        __syncthreads();

        for (int t = wid; t < 16; t += 8){
            int which = t >> 2, r = t & 3;
            float v;
            if (which == 0){
                float x1 = smB[640 + r*64 + lane], x2 = smB[640 + r*64 + lane + 32];
                v = x1*x1 + x2*x2;
            } else if (which == 1){
                float x1 = smA[r*64 + lane], x2 = smA[r*64 + lane + 32];
                v = x1*x1 + x2*x2;
            } else if (which == 2){
                float x1 = smA[256 + r*128 + 64 + lane], x2 = smA[256 + r*128 + 96 + lane];
                v = x1*x1 + x2*x2;
            } else {
                v = smA[r*64 + lane]      * smA[256 + r*128 + 64 + lane]
                  + smA[r*64 + lane + 32] * smA[256 + r*128 + 96 + lane];
            }
            #pragma unroll
            for (int s = 16; s > 0; s >>= 1) v += __shfl_down_sync(0xffffffffu, v, s);
            if (lane == 0) smD[270 + t] = v;
        }
        __syncthreads();
        {
            int r = quad;
            float invz  = 1.f / fmaxf(sqrtf(smD[270 + 0  + r]), 1e-8f);
            float invzt = 1.f / fmaxf(sqrtf(smD[270 + 4  + r]), 1e-8f);
            float invzg = 1.f / fmaxf(sqrtf(smD[270 + 8  + r]), 1e-8f);
            g_znorm[(base+r)*64 + c] = smB[640 + r*64 + c] * invz;
            g_qn[(base+r)*64 + c]    = smA[r*64 + c] * invzt;
            g_kn[(base+r)*64 + c]    = smA[256 + r*128 + 64 + c] * invzg;
            if (c == 0) g_diag[base+r] = 10.f * smD[270 + 12 + r] * invzt * invzg;
        }
        if (tid < 64){
            float ms = 0.f;
            #pragma unroll
            for (int r = 0; r < 4; r++){
                float invz = 1.f / fmaxf(sqrtf(smD[270 + r]), 1e-8f);
                ms += smB[640 + r*64 + tid] * invz;
            }
            atomicAdd(&g_meanacc[tid], ms);
        }
        __syncthreads();
    }

    gsync(G);

    // ================= PHASE 2a: aux =================
    if (tid < 64) smD[288 + tid] = __ldcg(&g_meanacc[tid]) * (1.f/2048.f);
    __syncthreads();
    if (wid == 0){
        float m1 = smD[288 + lane], m2 = smD[288 + lane + 32];
        float v = m1*m1 + m2*m2;
        #pragma unroll
        for (int s = 16; s > 0; s >>= 1) v += __shfl_down_sync(0xffffffffu, v, s);
        if (lane == 0) smD[286] = v;
    }
    __syncthreads();
    if (tid < 64){
        float inv = 1.f / fmaxf(sqrtf(smD[286]), 1e-8f);
        smD[352 + tid] = smD[288 + tid] * inv;
    }
    __syncthreads();

    float cw1 = smD[352 + lane], cw2 = smD[352 + lane + 32];
    float sdacc = 0.f;
    float tacc  = 0.f;
    for (int r = bid*8 + wid; r < NROW; r += G*8){
        float z1 = g_znorm[r*64 + lane];
        float z2 = g_znorm[r*64 + lane + 32];
        sdacc = fmaf(z1, cw1, fmaf(z2, cw2, sdacc));
        if ((r & 511) != 511){
            float y1 = g_znorm[(r+1)*64 + lane];
            float y2 = g_znorm[(r+1)*64 + lane + 32];
            float d = fmaf(z1, y1, z2*y2);
            #pragma unroll
            for (int s = 16; s > 0; s >>= 1) d += __shfl_down_sync(0xffffffffu, d, s);
            if (lane == 0){ float dd = 1.f - d; tacc = fmaf(dd, dd, tacc); }
        }
    }
    __syncthreads();
    smD[544 + tid] = sdacc; __syncthreads();
    #pragma unroll
    for (int s = 128; s > 0; s >>= 1){ if (tid < s) smD[544+tid] += smD[544+tid+s]; __syncthreads(); }
    if (tid == 0) atomicAdd(&g_scal[0], smD[544]);
    __syncthreads();
    smD[544 + tid] = (lane == 0) ? tacc : 0.f; __syncthreads();
    #pragma unroll
    for (int s = 128; s > 0; s >>= 1){ if (tid < s) smD[544+tid] += smD[544+tid+s]; __syncthreads(); }
    if (tid == 0) atomicAdd(&g_scal[1], smD[544]);
    __syncthreads();

    // ================= PHASE 2b: logits, 128x128 tiles, 8x8 micro ==========
    {
        float* qT = sm;            // [64][128]
        float* kT = sm + 8192;     // [64][128]
        float* colPart = sm + 16384; // [16][128]
        const int tx = tid & 15, ty = tid >> 4;

        for (int tI = bid; tI < 256; tI += G){
            int rb = (tI & 15) << 7, cb = (tI >> 4) << 7;

            __syncthreads();   // protect smem reuse from previous tile/phase
            for (int idx = tid; idx < 2048; idx += 256){
                int i = idx & 127, kg = idx >> 7;          // kg: 0..15
                float4 q4 = *(const float4*)&g_qn[(rb+i)*64 + kg*4];
                float4 k4 = *(const float4*)&g_kn[(cb+i)*64 + kg*4];
                qT[(kg*4+0)*128 + i] = q4.x;
                qT[(kg*4+1)*128 + i] = q4.y;
                qT[(kg*4+2)*128 + i] = q4.z;
                qT[(kg*4+3)*128 + i] = q4.w;
                kT[(kg*4+0)*128 + i] = k4.x;
                kT[(kg*4+1)*128 + i] = k4.y;
                kT[(kg*4+2)*128 + i] = k4.z;
                kT[(kg*4+3)*128 + i] = k4.w;
            }
            __syncthreads();

            float acc[8][8];
            #pragma unroll
            for (int a = 0; a < 8; a++)
                #pragma unroll
                for (int b = 0; b < 8; b++) acc[a][b] = 0.f;

            #pragma unroll 2
            for (int k = 0; k < 64; k++){
                float4 a0 = *(const float4*)&qT[k*128 + ty*4];
                float4 a1 = *(const float4*)&qT[k*128 + 64 + ty*4];
                float4 b0 = *(const float4*)&kT[k*128 + tx*4];
                float4 b1 = *(const float4*)&kT[k*128 + 64 + tx*4];
                float av[8] = {a0.x,a0.y,a0.z,a0.w, a1.x,a1.y,a1.z,a1.w};
                float bv[8] = {b0.x,b0.y,b0.z,b0.w, b1.x,b1.y,b1.z,b1.w};
                #pragma unroll
                for (int a = 0; a < 8; a++)
                    #pragma unroll
                    for (int b = 0; b < 8; b++)
                        acc[a][b] = fmaf(av[a], bv[b], acc[a][b]);
            }

            float rs[8] = {0,0,0,0,0,0,0,0};
            float cs[8] = {0,0,0,0,0,0,0,0};
            #pragma unroll
            for (int a = 0; a < 8; a++)
                #pragma unroll
                for (int b = 0; b < 8; b++){
                    float p = fexp(acc[a][b] * 10.f);
                    rs[a] += p; cs[b] += p;
                }

            // row reduce across tx (16-lane groups)
            #pragma unroll
            for (int a = 0; a < 8; a++){
                #pragma unroll
                for (int o = 8; o > 0; o >>= 1)
                    rs[a] += __shfl_xor_sync(0xffffffffu, rs[a], o);
            }
            if (tx == 0){
                #pragma unroll
                for (int a = 0; a < 8; a++){
                    int row = (a < 4) ? (ty*4 + a) : (64 + ty*4 + a - 4);
                    atomicAdd(&g_rowsum[rb + row], rs[a]);
                }
            }
            // col partials: exclusive slots, no atomics
            #pragma unroll
            for (int b = 0; b < 4; b++){
                colPart[ty*128 + tx*4 + b]      = cs[b];
                colPart[ty*128 + 64 + tx*4 + b] = cs[b+4];
            }
            __syncthreads();
            if (tid < 128){
                float s = 0.f;
                #pragma unroll
                for (int t = 0; t < 16; t++) s += colPart[t*128 + tid];
                atomicAdd(&g_colsum[cb + tid], s);
            }
        }
    }

    gsync(G);

    // ================= PHASE 3: final =================
    if (bid == 0){
        float s = 0.f;
        for (int r = tid; r < NROW; r += 256){
            float rsm = __ldcg(&g_rowsum[r]);
            float csm = __ldcg(&g_colsum[r]);
            float dg  = __ldcg(&g_diag[r]);
            s += logf(rsm) + logf(csm) - 2.f*dg;
        }
        smD[544 + tid] = s; __syncthreads();
        #pragma unroll
        for (int k = 128; k > 0; k >>= 1){ if (tid < k) smD[544+tid] += smD[544+tid+k]; __syncthreads(); }
        if (tid == 0){
            float l_con = 0.5f * smD[544] / 2048.f;
            float l_sc  = -__ldcg(&g_scal[0]) / 2048.f;
            float l_t   =  __ldcg(&g_scal[1]) / (4.f * 511.f);
            out[0] = l_con + l_sc + l_t;
            out[1] = l_con;
            out[2] = l_sc;
            out[3] = l_t;
        }
    }
}

// ---------------- launch ----------------
extern "C" void kernel_launch(void* const* d_in, const int* in_sizes, int n_in,
                              void* d_out, int out_size){
    const float* h      = (const float*)d_in[0];
    const float* x_raw  = (const float*)d_in[1];
    const float* W_in   = (const float*)d_in[2];
    const float* b_in   = (const float*)d_in[3];
    const float* dt_emb = (const float*)d_in[4];
    const float* Wm1    = (const float*)d_in[5];
    const float* bm1    = (const float*)d_in[6];
    const float* Wm2    = (const float*)d_in[7];
    const float* bm2    = (const float*)d_in[8];
    const float* Wg     = (const float*)d_in[9];
    const float* a1     = (const float*)d_in[10];
    const float* a2     = (const float*)d_in[11];
    const float* Wf     = (const float*)d_in[12];
    const float* bf     = (const float*)d_in[13];
    float* out = (float*)d_out;

    const int SMEM = 18432 * 4;   // 72KB dynamic
    cudaFuncSetAttribute(fused_kernel, cudaFuncAttributeMaxDynamicSharedMemorySize, SMEM);

    int dev = 0; cudaGetDevice(&dev);
    int sms = 0;
    cudaDeviceGetAttribute(&sms, cudaDevAttrMultiProcessorCount, dev);
    if (sms <= 0) sms = 148;
    int G = sms * 2;

    fused_kernel<<<G, 256, SMEM>>>(h, x_raw, W_in, b_in, dt_emb, Wm1, bm1, Wm2, bm2,
                                   Wg, a1, a2, Wf, bf, out);
}